// round 1
// baseline (speedup 1.0000x reference)
#include <cuda_runtime.h>
#include <math.h>

#define BATCH 8
#define SEQ   2048
#define DIM   1024
#define MROWS (BATCH * SEQ)   /* 16384 */
#define EPS   1e-6f

/* Scratch (allocation-free): 3 x 64 MB */
__device__ float g_xp  [(size_t)MROWS * DIM];
__device__ float g_wx  [(size_t)MROWS * DIM];
__device__ float g_outs[(size_t)MROWS * DIM];

/* ---------------------------------------------------------------------
 * SGEMM: C[m,n] = sum_k A[m,k] * W[n,k]   (A: [M,K] rm, W: [N,K] rm)
 * Tile 128x128x16, 256 threads, 8x8 per thread.
 * EPI: 0 = none, 1 = silu(c), 2 = c + bias[n]
 * M=16384, N=1024, K=1024 hardcoded-divisible; no bounds checks.
 * ------------------------------------------------------------------- */
template <int EPI>
__global__ __launch_bounds__(256, 2)
void sgemm_abt(const float* __restrict__ A,
               const float* __restrict__ W,
               const float* __restrict__ bias,
               float* __restrict__ C)
{
    constexpr int BM = 128, BN = 128, BK = 16;
    constexpr int K = DIM;

    __shared__ float As[BK][BM];
    __shared__ float Bs[BK][BN];

    const int tid = threadIdx.x;
    const int bm  = blockIdx.y;
    const int bn  = blockIdx.x;
    const int tn  = tid & 15;     // 0..15
    const int tm  = tid >> 4;     // 0..15

    const float* Ab = A + (size_t)bm * BM * K;
    const float* Wb = W + (size_t)bn * BN * K;

    float acc[8][8] = {};

    for (int k0 = 0; k0 < K; k0 += BK) {
        /* load A tile: 128 rows x 16 k = 512 float4, 2 per thread */
        #pragma unroll
        for (int i = 0; i < 2; i++) {
            int f   = tid + i * 256;
            int row = f >> 2;
            int kc  = (f & 3) * 4;
            float4 v = *(const float4*)(Ab + (size_t)row * K + k0 + kc);
            As[kc + 0][row] = v.x;
            As[kc + 1][row] = v.y;
            As[kc + 2][row] = v.z;
            As[kc + 3][row] = v.w;
        }
        /* load W tile: 128 rows x 16 k */
        #pragma unroll
        for (int i = 0; i < 2; i++) {
            int f   = tid + i * 256;
            int row = f >> 2;
            int kc  = (f & 3) * 4;
            float4 v = *(const float4*)(Wb + (size_t)row * K + k0 + kc);
            Bs[kc + 0][row] = v.x;
            Bs[kc + 1][row] = v.y;
            Bs[kc + 2][row] = v.z;
            Bs[kc + 3][row] = v.w;
        }
        __syncthreads();

        #pragma unroll
        for (int kk = 0; kk < BK; kk++) {
            float4 a0 = *(const float4*)&As[kk][tm * 8];
            float4 a1 = *(const float4*)&As[kk][tm * 8 + 4];
            float4 b0 = *(const float4*)&Bs[kk][tn * 8];
            float4 b1 = *(const float4*)&Bs[kk][tn * 8 + 4];
            float ra[8] = {a0.x, a0.y, a0.z, a0.w, a1.x, a1.y, a1.z, a1.w};
            float rb[8] = {b0.x, b0.y, b0.z, b0.w, b1.x, b1.y, b1.z, b1.w};
            #pragma unroll
            for (int i = 0; i < 8; i++)
                #pragma unroll
                for (int j = 0; j < 8; j++)
                    acc[i][j] = fmaf(ra[i], rb[j], acc[i][j]);
        }
        __syncthreads();
    }

    /* epilogue + store */
    #pragma unroll
    for (int i = 0; i < 8; i++) {
        const size_t m = (size_t)bm * BM + tm * 8 + i;
        #pragma unroll
        for (int j = 0; j < 8; j += 4) {
            const int n = bn * BN + tn * 8 + j;
            float c0 = acc[i][j + 0];
            float c1 = acc[i][j + 1];
            float c2 = acc[i][j + 2];
            float c3 = acc[i][j + 3];
            if (EPI == 1) { /* silu */
                c0 = c0 / (1.0f + __expf(-c0));
                c1 = c1 / (1.0f + __expf(-c1));
                c2 = c2 / (1.0f + __expf(-c2));
                c3 = c3 / (1.0f + __expf(-c3));
            } else if (EPI == 2) { /* + bias */
                c0 += bias[n + 0];
                c1 += bias[n + 1];
                c2 += bias[n + 2];
                c3 += bias[n + 3];
            }
            float4 v = make_float4(c0, c1, c2, c3);
            *(float4*)(C + m * DIM + n) = v;
        }
    }
}

/* ---------------------------------------------------------------------
 * Recurrence: one block per batch, 256 threads, 4 elems (float4) each.
 *   h_new = h + alpha * wx
 *   h_new = h_new * rsqrt(mean(h_new^2) + eps)
 *   out   = h_new * silu(h_new) = h_new^2 * sigmoid(h_new)
 * h stays in registers across all T steps.
 * ------------------------------------------------------------------- */
__global__ __launch_bounds__(256, 1)
void recurrence_kernel(const float* __restrict__ h0,
                       const float* __restrict__ log_alpha,
                       float* __restrict__ h_final)
{
    const int b   = blockIdx.x;
    const int tid = threadIdx.x;
    const float alpha = __expf(log_alpha[0]);

    __shared__ float red[8];

    float4 h = ((const float4*)(h0 + (size_t)b * DIM))[tid];

    const float4* wxp  = (const float4*)(g_wx   + (size_t)b * SEQ * DIM);
    float4*       outp = (float4*)      (g_outs + (size_t)b * SEQ * DIM);

    float4 wx = wxp[tid];   /* t = 0 prefetched */

    for (int t = 0; t < SEQ; t++) {
        /* prefetch next step's wx early — hides global latency behind reduce */
        float4 wxn = make_float4(0.f, 0.f, 0.f, 0.f);
        if (t + 1 < SEQ) wxn = wxp[(size_t)(t + 1) * 256 + tid];

        h.x = fmaf(alpha, wx.x, h.x);
        h.y = fmaf(alpha, wx.y, h.y);
        h.z = fmaf(alpha, wx.z, h.z);
        h.w = fmaf(alpha, wx.w, h.w);

        float s = h.x * h.x + h.y * h.y + h.z * h.z + h.w * h.w;
        #pragma unroll
        for (int o = 16; o > 0; o >>= 1)
            s += __shfl_xor_sync(0xFFFFFFFFu, s, o);

        __syncthreads();                 /* protect red[] from prev iter's readers */
        if ((tid & 31) == 0) red[tid >> 5] = s;
        __syncthreads();

        float tot = red[0] + red[1] + red[2] + red[3]
                  + red[4] + red[5] + red[6] + red[7];
        float r = rsqrtf(tot * (1.0f / DIM) + EPS);

        h.x *= r; h.y *= r; h.z *= r; h.w *= r;

        float4 o4;
        o4.x = h.x * h.x / (1.0f + __expf(-h.x));
        o4.y = h.y * h.y / (1.0f + __expf(-h.y));
        o4.z = h.z * h.z / (1.0f + __expf(-h.z));
        o4.w = h.w * h.w / (1.0f + __expf(-h.w));
        outp[(size_t)t * 256 + tid] = o4;

        wx = wxn;
    }

    ((float4*)(h_final + (size_t)b * DIM))[tid] = h;
}

extern "C" void kernel_launch(void* const* d_in, const int* in_sizes, int n_in,
                              void* d_out, int out_size)
{
    const float* x         = (const float*)d_in[0];   /* [8,2048,1024] */
    const float* h0        = (const float*)d_in[1];   /* [8,1024]      */
    const float* W_in      = (const float*)d_in[2];   /* [1024,1024]   */
    const float* W_cell    = (const float*)d_in[3];   /* [1024,1024]   */
    const float* b_cell    = (const float*)d_in[4];   /* [1024]        */
    const float* log_alpha = (const float*)d_in[5];   /* scalar        */
    const float* W_out     = (const float*)d_in[6];   /* [1024,1024]   */

    float* y  = (float*)d_out;                        /* [8,2048,1024] */
    float* hf = y + (size_t)MROWS * DIM;              /* [8,1024]      */

    float *xp, *wx, *outs;
    cudaGetSymbolAddress((void**)&xp,   g_xp);
    cudaGetSymbolAddress((void**)&wx,   g_wx);
    cudaGetSymbolAddress((void**)&outs, g_outs);

    dim3 grid(DIM / 128, MROWS / 128);   /* (8, 128) */
    dim3 blk(256);

    /* 1. xp = silu(x @ W_in^T) */
    sgemm_abt<1><<<grid, blk>>>(x, W_in, nullptr, xp);
    /* 2. Wx = xp @ W_cell^T + b_cell */
    sgemm_abt<2><<<grid, blk>>>(xp, W_cell, b_cell, wx);
    /* 3. scan */
    recurrence_kernel<<<BATCH, 256>>>(h0, log_alpha, hf);
    /* 4. y = outs @ W_out^T */
    sgemm_abt<0><<<grid, blk>>>(outs, W_out, nullptr, y);
}